// round 12
// baseline (speedup 1.0000x reference)
#include <cuda_runtime.h>

typedef unsigned long long u64;

#define N_Q   9
#define C_CH  3
#define LEN   2048
#define LOUT  2046
#define BATCH 8
#define OCH   8
#define WPB   8
#define WU64  832                        // 574 transpose + 256 packed base (u64)
#define DYNSZ (WPB * WU64 * 8)           // 53248 bytes dynamic smem

// ---------- packed f32x2 helpers ----------
__device__ __forceinline__ u64 pk2(float lo, float hi){
    u64 r; asm("mov.b64 %0, {%1, %2};" : "=l"(r) : "f"(lo), "f"(hi)); return r;
}
__device__ __forceinline__ float lo2(u64 v){
    float a; asm("{.reg .b32 h_; mov.b64 {%0, h_}, %1;}" : "=f"(a) : "l"(v)); return a;
}
__device__ __forceinline__ float hi2(u64 v){
    float a; asm("{.reg .b32 l_; mov.b64 {l_, %0}, %1;}" : "=f"(a) : "l"(v)); return a;
}
__device__ __forceinline__ u64 fma2(u64 a, u64 b, u64 c){
    u64 d; asm("fma.rn.f32x2 %0, %1, %2, %3;" : "=l"(d) : "l"(a), "l"(b), "l"(c)); return d;
}

// CNOT-ring permutation (replicates reference idx construction)
__device__ __forceinline__ int permref(int id){
#pragma unroll
    for (int c = 0; c < N_Q - 1; ++c){
        const int bit = (id >> (N_Q - 1 - c)) & 1;
        id ^= bit << (N_Q - 2 - c);
    }
    id ^= (id & 1) << (N_Q - 1);
    return id;
}

__global__ __launch_bounds__(256, 4)
void qconv_kernel(const float* __restrict__ x,
                  const float* __restrict__ theta,
                  float* __restrict__ out)
{
    extern __shared__ __align__(16) u64 dyn[];
    __shared__ u64   gttp[OCH / 2][8];   // (tan_o, tan_{o+1}) per qubit qi=0..7
    __shared__ float gtan[OCH][8];
    __shared__ float gc2[OCH * 8];
    __shared__ float gK[OCH];

    const int tid  = threadIdx.x;
    const int warp = tid >> 5;
    const int lane = tid & 31;
    const int t    = blockIdx.x >> 1;    // window position
    const int half = blockIdx.x & 1;     // channel half: channels 4h..4h+3
    const int b    = warp;               // batch

    // ---- gate prep: phi = pi/4 - theta/2, tangent form ----
    if (tid < OCH * 8){
        const int o = tid >> 3, qi = tid & 7;          // qubit = qi+1
        const float th  = theta[o * N_Q + qi + 1];
        const float phi = 0.78539816339744830962f - 0.5f * th;
        float s, c; __sincosf(phi, &s, &c);
        gtan[o][qi] = __fdividef(s, c);
        gc2[tid]    = c * c;
    }
    __syncthreads();
    if (tid < 32){
        const int pr = tid >> 3, qi = tid & 7;
        gttp[pr][qi] = pk2(gtan[2 * pr][qi], gtan[2 * pr + 1][qi]);
    }
    if (tid < OCH){
        float k = 1.0f;
#pragma unroll
        for (int q = 0; q < 8; ++q) k *= gc2[tid * 8 + q];
        gK[tid] = k;
    }
    __syncthreads();

    u64*   S64   = dyn + warp * WU64;
    float* SF    = (float*)S64;
    u64*   BASE  = S64 + 576;            // packed layout-A base (576..831)
    float* BASEF = (float*)BASE;
    const int llo = lane & 15;
    const int l4  = lane >> 4;

    // ---- WHT-domain per-qubit factors ----
    float av[N_Q], bv[N_Q];
#pragma unroll
    for (int i = 0; i < N_Q; ++i){
        const float xv = x[(b * C_CH + i / 3) * LEN + t + (i % 3)];
        float s, c; __sincosf(0.5f * xv, &s, &c);
        av[i] = c + s;
        bv[i] = c - s;
    }

    // ---- WHT(state) as product state, pre-scatter layout (scalar v[16]) ----
    float lf = 0.044194173824159220275f;     // 1/sqrt(512)
    lf *= l4        ? bv[0] : av[0];
    lf *= (llo & 1) ? bv[8] : av[8];
    lf *= (llo & 2) ? bv[7] : av[7];
    lf *= (llo & 4) ? bv[6] : av[6];
    lf *= (llo & 8) ? bv[5] : av[5];

    float v[16];
    v[0] = lf;
#pragma unroll
    for (int bp = 0; bp < 4; ++bp){          // r bit bp -> qubit 4-bp
        const int q  = 4 - bp;
        const int sz = 1 << bp;
#pragma unroll
        for (int u = 0; u < 8; ++u) if (u < sz){
            v[u + sz] = v[u] * bv[q];
            v[u]      = v[u] * av[q];
        }
    }

    // ---- scatter through CNOT-ring perm DIRECTLY into packed layout A ----
    // slot(j) = (j[8:4] ^ j[3:1]) + 32*j[3:1], half-of-u64 = j[0]. Conflict-free.
    const int pbase = permref((l4 << 8) | llo);
#pragma unroll
    for (int r = 0; r < 16; ++r){
        const int j   = pbase ^ permref(r << 4);
        const int j31 = (j >> 1) & 7;
        const int sl  = ((j >> 4) ^ j31) + 32 * j31;
        BASEF[2 * sl + (j & 1)] = v[r];
    }
    __syncwarp();

    // ---- channel pairs (only this block-half's two pairs) ----
    const float tsgn = (__popc(llo & 7) & 1) ? -1.0f : 1.0f;
    const int   s8   = llo >> 3;               // read-side bit3 relabel flag
    const u64   FLIPB = 0x8000000080000000ULL;

    // compact u64 transpose map: addr = (j7..4 ^ 8*j3) + 18*j3..0 + 288*j8
    u64* W0 = S64 + llo + 288 * l4;            // writes r<8  : W0[18r]
    u64* W1 = S64 + (llo ^ 8) + 288 * l4;      // writes r>=8 : W1[18r]
    const ulonglong2* RB = (const ulonglong2*)(S64 + 18 * llo + 288 * l4);

    u64 P[2];

#pragma unroll
    for (int pp = 0; pp < 2; ++pp){
        const int pr = 2 * half + pp;
        const int o  = 2 * pr;
        u64 Z[16];

        // qubit 8 (reg bit0) fused with pair init from packed base
        {
            const float ta = gtan[o][7], tb_ = gtan[o + 1][7];
#pragma unroll
            for (int p = 0; p < 8; ++p){
                const u64 w  = BASE[(lane ^ p) + 32 * p];
                const float a0 = lo2(w), b0 = hi2(w);
                Z[2 * p]     = pk2(fmaf( ta, b0, a0), fmaf( tb_, b0, a0));
                Z[2 * p + 1] = pk2(fmaf(-ta, a0, b0), fmaf(-tb_, a0, b0));
            }
        }
        // qubits 7,6,5 (reg bits 1,2,3)
#pragma unroll
        for (int k = 1; k < 4; ++k){
            const int m   = 1 << k;
            const u64 tb  = gttp[pr][7 - k];
            const u64 ntb = tb ^ FLIPB;
#pragma unroll
            for (int p = 0; p < 16; ++p) if (!(p & m)){
                const u64 A = Z[p], B = Z[p | m];
                Z[p]     = fma2(tb,  B, A);
                Z[p | m] = fma2(ntb, A, B);
            }
        }

        // u64 transpose (swap j7..4 <-> j3..0), conflict-free both directions
        __syncwarp();
#pragma unroll
        for (int r = 0; r < 8; ++r)  W0[18 * r] = Z[r];
#pragma unroll
        for (int r = 8; r < 16; ++r) W1[18 * r] = Z[r];
        __syncwarp();

        // read + fused qubit-4 rotation (new reg bit0)
        {
            const u64 tb4  = gttp[pr][3];
            const u64 ntb4 = tb4 ^ FLIPB;
#pragma unroll
            for (int kk = 0; kk < 8; ++kk){
                const ulonglong2 w = RB[kk];
                Z[2 * kk]     = fma2(tb4,  w.y, w.x);
                Z[2 * kk + 1] = fma2(ntb4, w.x, w.y);
            }
        }
        // qubits 3,2 (reg bits 1,2)
#pragma unroll
        for (int k = 1; k < 3; ++k){
            const int m   = 1 << k;
            const u64 tb  = gttp[pr][3 - k];
            const u64 ntb = tb ^ FLIPB;
#pragma unroll
            for (int p = 0; p < 16; ++p) if (!(p & m)){
                const u64 A = Z[p], B = Z[p | m];
                Z[p]     = fma2(tb,  B, A);
                Z[p | m] = fma2(ntb, A, B);
            }
        }
        // qubit 1 (reg bit 3) with s8 role swap (k = r' ^ 8*s8)
        {
            const u64 tb1  = gttp[pr][0];
            const u64 ntb1 = tb1 ^ FLIPB;
            const u64 ta   = s8 ? ntb1 : tb1;
            const u64 tb_  = s8 ? tb1  : ntb1;
#pragma unroll
            for (int p = 0; p < 8; ++p){
                const u64 A = Z[p], B = Z[p | 8];
                Z[p]     = fma2(ta,  B, A);
                Z[p | 8] = fma2(tb_, A, B);
            }
        }

        // signed squares: sign(j) = tsgn * (-1)^popc4(k)
        u64 accE = 0, accO = 0;
        accE = fma2(Z[0],  Z[0],  accE);  accO = fma2(Z[1],  Z[1],  accO);
        accO = fma2(Z[2],  Z[2],  accO);  accE = fma2(Z[3],  Z[3],  accE);
        accO = fma2(Z[4],  Z[4],  accO);  accE = fma2(Z[5],  Z[5],  accE);
        accE = fma2(Z[6],  Z[6],  accE);  accO = fma2(Z[7],  Z[7],  accO);
        accO = fma2(Z[8],  Z[8],  accO);  accE = fma2(Z[9],  Z[9],  accE);
        accE = fma2(Z[10], Z[10], accE);  accO = fma2(Z[11], Z[11], accO);
        accE = fma2(Z[12], Z[12], accE);  accO = fma2(Z[13], Z[13], accO);
        accO = fma2(Z[14], Z[14], accO);  accE = fma2(Z[15], Z[15], accE);

        P[pp] = pk2((lo2(accE) - lo2(accO)) * tsgn,
                    (hi2(accE) - hi2(accO)) * tsgn);
    }

    // ---- partials into (now free) transpose region; local channels c=0..3 ----
    __syncwarp();
#pragma unroll
    for (int pp = 0; pp < 2; ++pp){
        const int c = 2 * pp;
        SF[c * 36       + ((lane + c)     & 31)] = lo2(P[pp]);
        SF[(c + 1) * 36 + ((lane + c + 1) & 31)] = hi2(P[pp]);
    }
    __syncwarp();

    // ---- cooperative 4-channel reduction: 4 LDS + 3 SHFL per thread ----
    {
        const int c = lane >> 3;          // local channel 0..3
        const int i = lane & 7;
        float tot = 0.0f;
#pragma unroll
        for (int m = 0; m < 4; ++m)
            tot += SF[c * 36 + ((4 * i + m + c) & 31)];
        tot += __shfl_xor_sync(0xffffffffu, tot, 1);
        tot += __shfl_xor_sync(0xffffffffu, tot, 2);
        tot += __shfl_xor_sync(0xffffffffu, tot, 4);
        if (i == 0){
            const int ch = 4 * half + c;
            out[(b * OCH + ch) * LOUT + t] = tot * gK[ch];
        }
    }
}

extern "C" void kernel_launch(void* const* d_in, const int* in_sizes, int n_in,
                              void* d_out, int out_size)
{
    const float* x_ptr  = nullptr;
    const float* th_ptr = nullptr;
    for (int i = 0; i < n_in; ++i){
        if (in_sizes[i] == BATCH * C_CH * LEN) x_ptr  = (const float*)d_in[i];
        else if (in_sizes[i] == OCH * N_Q)     th_ptr = (const float*)d_in[i];
    }
    if (!x_ptr)  x_ptr  = (const float*)d_in[0];
    if (!th_ptr) th_ptr = (const float*)d_in[n_in - 1];

    cudaFuncSetAttribute(qconv_kernel,
                         cudaFuncAttributeMaxDynamicSharedMemorySize, DYNSZ);
    qconv_kernel<<<2 * LOUT, 256, DYNSZ>>>(x_ptr, th_ptr, (float*)d_out);
}

// round 13
// speedup vs baseline: 1.1260x; 1.1260x over previous
#include <cuda_runtime.h>

typedef unsigned long long u64;

#define N_Q   9
#define C_CH  3
#define LEN   2048
#define LOUT  2046
#define BATCH 8
#define OCH   8
#define WPB   8
#define WU64  832                        // 574 transpose/scatter + 256 bse spill (u64)
#define DYNSZ (WPB * WU64 * 8)           // 53248 bytes dynamic smem

// ---------- packed f32x2 helpers ----------
__device__ __forceinline__ u64 pk2(float lo, float hi){
    u64 r; asm("mov.b64 %0, {%1, %2};" : "=l"(r) : "f"(lo), "f"(hi)); return r;
}
__device__ __forceinline__ float lo2(u64 v){
    float a; asm("{.reg .b32 h_; mov.b64 {%0, h_}, %1;}" : "=f"(a) : "l"(v)); return a;
}
__device__ __forceinline__ float hi2(u64 v){
    float a; asm("{.reg .b32 l_; mov.b64 {l_, %0}, %1;}" : "=f"(a) : "l"(v)); return a;
}
__device__ __forceinline__ u64 fma2(u64 a, u64 b, u64 c){
    u64 d; asm("fma.rn.f32x2 %0, %1, %2, %3;" : "=l"(d) : "l"(a), "l"(b), "l"(c)); return d;
}

// CNOT-ring permutation (replicates reference idx construction)
__device__ __forceinline__ int permref(int id){
#pragma unroll
    for (int c = 0; c < N_Q - 1; ++c){
        const int bit = (id >> (N_Q - 1 - c)) & 1;
        id ^= bit << (N_Q - 2 - c);
    }
    id ^= (id & 1) << (N_Q - 1);
    return id;
}

// float map for the perm scatter (validated R6/R7/R9)
__device__ __forceinline__ int smf(int j){
    return (j & 15) + 34 * ((j >> 4) & 15) + 560 * (j >> 8);
}

__global__ __launch_bounds__(256, 4)
void qconv_kernel(const float* __restrict__ x,
                  const float* __restrict__ theta,
                  float* __restrict__ out)
{
    extern __shared__ __align__(16) u64 dyn[];
    __shared__ u64   gttp[OCH / 2][8];   // (tan_o, tan_{o+1}) per qubit qi=0..7
    __shared__ float gtan[OCH][8];
    __shared__ float gc2[OCH * 8];
    __shared__ float gK[OCH];

    const int tid  = threadIdx.x;
    const int warp = tid >> 5;
    const int lane = tid & 31;
    const int t    = blockIdx.x;         // window position
    const int b    = warp;               // batch

    // ---- gate prep: phi = pi/4 - theta/2, tangent form ----
    if (tid < OCH * 8){
        const int o = tid >> 3, qi = tid & 7;          // qubit = qi+1
        const float th  = theta[o * N_Q + qi + 1];
        const float phi = 0.78539816339744830962f - 0.5f * th;
        float s, c; __sincosf(phi, &s, &c);
        gtan[o][qi] = __fdividef(s, c);
        gc2[tid]    = c * c;
    }
    __syncthreads();
    if (tid < 32){
        const int pr = tid >> 3, qi = tid & 7;
        gttp[pr][qi] = pk2(gtan[2 * pr][qi], gtan[2 * pr + 1][qi]);
    }
    if (tid < OCH){
        float k = 1.0f;
#pragma unroll
        for (int q = 0; q < 8; ++q) k *= gc2[tid * 8 + q];
        gK[tid] = k;
    }
    __syncthreads();

    u64*   S64   = dyn + warp * WU64;
    float* SF    = (float*)S64;
    u64*   SPILL = S64 + 576;            // bse spill region (576..831, disjoint)
    const int llo = lane & 15;
    const int l4  = lane >> 4;

    // ---- WHT-domain per-qubit factors ----
    float av[N_Q], bv[N_Q];
#pragma unroll
    for (int i = 0; i < N_Q; ++i){
        const float xv = x[(b * C_CH + i / 3) * LEN + t + (i % 3)];
        float s, c; __sincosf(0.5f * xv, &s, &c);
        av[i] = c + s;
        bv[i] = c - s;
    }

    // ---- WHT(state) as product state, pre-scatter layout (scalar v[16]) ----
    float lf = 0.044194173824159220275f;     // 1/sqrt(512)
    lf *= l4        ? bv[0] : av[0];
    lf *= (llo & 1) ? bv[8] : av[8];
    lf *= (llo & 2) ? bv[7] : av[7];
    lf *= (llo & 4) ? bv[6] : av[6];
    lf *= (llo & 8) ? bv[5] : av[5];

    float v[16];
    v[0] = lf;
#pragma unroll
    for (int bp = 0; bp < 4; ++bp){          // r bit bp -> qubit 4-bp
        const int q  = 4 - bp;
        const int sz = 1 << bp;
#pragma unroll
        for (int u = 0; u < 8; ++u) if (u < sz){
            v[u + sz] = v[u] * bv[q];
            v[u]      = v[u] * av[q];
        }
    }

    // ---- scatter through CNOT-ring perm ----
    const int pbase = permref((l4 << 8) | llo);
#pragma unroll
    for (int r = 0; r < 16; ++r)
        SF[smf(pbase ^ permref(r << 4))] = v[r];
    __syncwarp();

    // ---- read base (layout A); keep in regs for pair 0, spill for pairs 1..3 ----
    u64 bse[8];
    {
        const float2* R = (const float2*)(SF + 34 * llo + 560 * l4);
#pragma unroll
        for (int p = 0; p < 8; ++p){
            const float2 w = R[p];
            bse[p] = pk2(w.x, w.y);
            SPILL[lane + 32 * p] = bse[p];
        }
    }

    // ---- channel pairs ----
    const float tsgn = (__popc(llo & 7) & 1) ? -1.0f : 1.0f;
    const int   s8   = llo >> 3;               // read-side bit3 relabel flag
    const u64   FLIPB = 0x8000000080000000ULL;

    // compact u64 transpose map: addr = (j7..4 ^ 8*j3) + 18*j3..0 + 288*j8
    u64* W0 = S64 + llo + 288 * l4;            // writes r<8  : W0[18r]
    u64* W1 = S64 + (llo ^ 8) + 288 * l4;      // writes r>=8 : W1[18r]
    const ulonglong2* RB = (const ulonglong2*)(S64 + 18 * llo + 288 * l4);

    u64 P[4];

#pragma unroll
    for (int pr = 0; pr < 4; ++pr){
        const int o = 2 * pr;
        u64 Z[16];

        // qubit 8 (reg bit0) fused with pair init (regs for pr=0, spill after)
        {
            const float ta = gtan[o][7], tb_ = gtan[o + 1][7];
#pragma unroll
            for (int p = 0; p < 8; ++p){
                const u64 w = (pr == 0) ? bse[p] : SPILL[lane + 32 * p];
                const float a0 = lo2(w), b0 = hi2(w);
                Z[2 * p]     = pk2(fmaf( ta, b0, a0), fmaf( tb_, b0, a0));
                Z[2 * p + 1] = pk2(fmaf(-ta, a0, b0), fmaf(-tb_, a0, b0));
            }
        }
        // qubits 7,6,5 (reg bits 1,2,3)
#pragma unroll
        for (int k = 1; k < 4; ++k){
            const int m   = 1 << k;
            const u64 tb  = gttp[pr][7 - k];
            const u64 ntb = tb ^ FLIPB;
#pragma unroll
            for (int p = 0; p < 16; ++p) if (!(p & m)){
                const u64 A = Z[p], B = Z[p | m];
                Z[p]     = fma2(tb,  B, A);
                Z[p | m] = fma2(ntb, A, B);
            }
        }

        // u64 transpose (swap j7..4 <-> j3..0), conflict-free both directions
        __syncwarp();
#pragma unroll
        for (int r = 0; r < 8; ++r)  W0[18 * r] = Z[r];
#pragma unroll
        for (int r = 8; r < 16; ++r) W1[18 * r] = Z[r];
        __syncwarp();

        // read + fused qubit-4 rotation (new reg bit0)
        {
            const u64 tb4  = gttp[pr][3];
            const u64 ntb4 = tb4 ^ FLIPB;
#pragma unroll
            for (int kk = 0; kk < 8; ++kk){
                const ulonglong2 w = RB[kk];
                Z[2 * kk]     = fma2(tb4,  w.y, w.x);
                Z[2 * kk + 1] = fma2(ntb4, w.x, w.y);
            }
        }
        // qubits 3,2 (reg bits 1,2)
#pragma unroll
        for (int k = 1; k < 3; ++k){
            const int m   = 1 << k;
            const u64 tb  = gttp[pr][3 - k];
            const u64 ntb = tb ^ FLIPB;
#pragma unroll
            for (int p = 0; p < 16; ++p) if (!(p & m)){
                const u64 A = Z[p], B = Z[p | m];
                Z[p]     = fma2(tb,  B, A);
                Z[p | m] = fma2(ntb, A, B);
            }
        }
        // qubit 1 (reg bit 3) with s8 role swap (k = r' ^ 8*s8)
        {
            const u64 tb1  = gttp[pr][0];
            const u64 ntb1 = tb1 ^ FLIPB;
            const u64 ta   = s8 ? ntb1 : tb1;
            const u64 tb_  = s8 ? tb1  : ntb1;
#pragma unroll
            for (int p = 0; p < 8; ++p){
                const u64 A = Z[p], B = Z[p | 8];
                Z[p]     = fma2(ta,  B, A);
                Z[p | 8] = fma2(tb_, A, B);
            }
        }

        // signed squares: sign(j) = tsgn * (-1)^popc4(k)
        u64 accE = 0, accO = 0;
        accE = fma2(Z[0],  Z[0],  accE);  accO = fma2(Z[1],  Z[1],  accO);
        accO = fma2(Z[2],  Z[2],  accO);  accE = fma2(Z[3],  Z[3],  accE);
        accO = fma2(Z[4],  Z[4],  accO);  accE = fma2(Z[5],  Z[5],  accE);
        accE = fma2(Z[6],  Z[6],  accE);  accO = fma2(Z[7],  Z[7],  accO);
        accO = fma2(Z[8],  Z[8],  accO);  accE = fma2(Z[9],  Z[9],  accE);
        accE = fma2(Z[10], Z[10], accE);  accO = fma2(Z[11], Z[11], accO);
        accE = fma2(Z[12], Z[12], accE);  accO = fma2(Z[13], Z[13], accO);
        accO = fma2(Z[14], Z[14], accO);  accE = fma2(Z[15], Z[15], accE);

        P[pr] = pk2((lo2(accE) - lo2(accO)) * tsgn,
                    (hi2(accE) - hi2(accO)) * tsgn);
    }

    // ---- partials into (now free) transpose region, validated swizzle ----
    __syncwarp();
#pragma unroll
    for (int pr = 0; pr < 4; ++pr){
        const int o = 2 * pr;
        SF[o * 36       + ((lane + o)     & 31)] = lo2(P[pr]);
        SF[(o + 1) * 36 + ((lane + o + 1) & 31)] = hi2(P[pr]);
    }
    __syncwarp();

    // ---- cooperative 8-channel reduction: 8 LDS + 2 SHFL per thread ----
    {
        const int ch = lane >> 2;
        const int i  = lane & 3;
        float tot = 0.0f;
#pragma unroll
        for (int m = 0; m < 8; ++m)
            tot += SF[ch * 36 + ((8 * i + m + ch) & 31)];
        tot += __shfl_xor_sync(0xffffffffu, tot, 1);
        tot += __shfl_xor_sync(0xffffffffu, tot, 2);
        if (i == 0)
            out[(b * OCH + ch) * LOUT + t] = tot * gK[ch];
    }
}

extern "C" void kernel_launch(void* const* d_in, const int* in_sizes, int n_in,
                              void* d_out, int out_size)
{
    const float* x_ptr  = nullptr;
    const float* th_ptr = nullptr;
    for (int i = 0; i < n_in; ++i){
        if (in_sizes[i] == BATCH * C_CH * LEN) x_ptr  = (const float*)d_in[i];
        else if (in_sizes[i] == OCH * N_Q)     th_ptr = (const float*)d_in[i];
    }
    if (!x_ptr)  x_ptr  = (const float*)d_in[0];
    if (!th_ptr) th_ptr = (const float*)d_in[n_in - 1];

    cudaFuncSetAttribute(qconv_kernel,
                         cudaFuncAttributeMaxDynamicSharedMemorySize, DYNSZ);
    qconv_kernel<<<LOUT, 256, DYNSZ>>>(x_ptr, th_ptr, (float*)d_out);
}

// round 14
// speedup vs baseline: 1.1337x; 1.0069x over previous
#include <cuda_runtime.h>

typedef unsigned long long u64;

#define N_Q   9
#define C_CH  3
#define LEN   2048
#define LOUT  2046
#define BATCH 8
#define OCH   8
#define WPB   8
#define WU64  832                        // 574 transpose + 256 bse spill (u64)
#define DYNSZ (WPB * WU64 * 8)           // 53248 bytes dynamic smem

// ---------- packed f32x2 helpers ----------
__device__ __forceinline__ u64 pk2(float lo, float hi){
    u64 r; asm("mov.b64 %0, {%1, %2};" : "=l"(r) : "f"(lo), "f"(hi)); return r;
}
__device__ __forceinline__ float lo2(u64 v){
    float a; asm("{.reg .b32 h_; mov.b64 {%0, h_}, %1;}" : "=f"(a) : "l"(v)); return a;
}
__device__ __forceinline__ float hi2(u64 v){
    float a; asm("{.reg .b32 l_; mov.b64 {l_, %0}, %1;}" : "=f"(a) : "l"(v)); return a;
}
__device__ __forceinline__ u64 fma2(u64 a, u64 b, u64 c){
    u64 d; asm("fma.rn.f32x2 %0, %1, %2, %3;" : "=l"(d) : "l"(a), "l"(b), "l"(c)); return d;
}

__global__ __launch_bounds__(256, 4)
void qconv_kernel(const float* __restrict__ x,
                  const float* __restrict__ theta,
                  float* __restrict__ out)
{
    extern __shared__ __align__(16) u64 dyn[];
    __shared__ u64   gttp[OCH / 2][8];   // (tan_o, tan_{o+1}) per qubit qi=0..7
    __shared__ float gtan[OCH][8];
    __shared__ float gc2[OCH * 8];
    __shared__ float gK[OCH];

    const int tid  = threadIdx.x;
    const int warp = tid >> 5;
    const int lane = tid & 31;
    const int t    = blockIdx.x;         // window position
    const int b    = warp;               // batch

    // ---- gate prep: phi = pi/4 - theta/2, tangent form ----
    if (tid < OCH * 8){
        const int o = tid >> 3, qi = tid & 7;          // qubit = qi+1
        const float th  = theta[o * N_Q + qi + 1];
        const float phi = 0.78539816339744830962f - 0.5f * th;
        float s, c; __sincosf(phi, &s, &c);
        gtan[o][qi] = __fdividef(s, c);
        gc2[tid]    = c * c;
    }
    __syncthreads();
    if (tid < 32){
        const int pr = tid >> 3, qi = tid & 7;
        gttp[pr][qi] = pk2(gtan[2 * pr][qi], gtan[2 * pr + 1][qi]);
    }
    if (tid < OCH){
        float k = 1.0f;
#pragma unroll
        for (int q = 0; q < 8; ++q) k *= gc2[tid * 8 + q];
        gK[tid] = k;
    }
    __syncthreads();

    u64*   S64   = dyn + warp * WU64;
    float* SF    = (float*)S64;
    u64*   SPILL = S64 + 576;            // bse spill region (576..831, disjoint)
    const int llo = lane & 15;
    const int l4  = lane >> 4;

    // ---- WHT-domain per-qubit factors: av = c+s (bit 0), bv = c-s (bit 1) ----
    float av[N_Q], bv[N_Q];
#pragma unroll
    for (int i = 0; i < N_Q; ++i){
        const float xv = x[(b * C_CH + i / 3) * LEN + t + (i % 3)];
        float s, c; __sincosf(0.5f * xv, &s, &c);
        av[i] = c + s;
        bv[i] = c - s;
    }

    // ---- build base state DIRECTLY in layout A (j = lane<<4 | r) ----
    // Element value = scale * prod_q f_q(x_{8-q}) where x = P^{-1}(j), with
    //   x_k = y_k ^ y_{k+1} (k<=6), x_7 = y7^y0^y8, x_8 = y0^y8   (y = j bits)
    // => qubit2: llo2^llo3, qubit3: llo1^llo2, qubit4: llo0^llo1,
    //    qubit5: r3^llo0, qubit6: r2^r3, qubit7: r1^r2, qubit8: r0^r1,
    //    qubit0: r0^l4, qubit1: r0^l4^llo3.
    const int s0 = llo & 1, s3 = (llo >> 3) & 1;
    const int q2b = ((llo >> 2) ^ (llo >> 3)) & 1;
    const int q3b = ((llo >> 1) ^ (llo >> 2)) & 1;
    const int q4b = (llo ^ (llo >> 1)) & 1;

    float lfc = 0.044194173824159220275f            // 1/sqrt(512)
              * (q2b ? bv[2] : av[2])
              * (q3b ? bv[3] : av[3])
              * (q4b ? bv[4] : av[4]);

    const float h0 = (l4 ? bv[0] : av[0]) * ((l4 ^ s3) ? bv[1] : av[1]); // r0=0
    const float h1 = (l4 ? av[0] : bv[0]) * ((l4 ^ s3) ? av[1] : bv[1]); // r0=1
    const float A0 = lfc * h0, A1 = lfc * h1;

    // qubit8 on r0^r1
    const float B00 = A0 * av[8], B01 = A1 * bv[8];
    const float B10 = A0 * bv[8], B11 = A1 * av[8];
    // qubit7 on r1^r2: C[r2][r1][r0]
    const float C000 = B00*av[7], C001 = B01*av[7], C010 = B10*bv[7], C011 = B11*bv[7];
    const float C100 = B00*bv[7], C101 = B01*bv[7], C110 = B10*av[7], C111 = B11*av[7];
    // qubit6 (r2^r3) * qubit5 (r3^llo0): D[r3][r2]
    const float f50 = s0 ? bv[5] : av[5];
    const float f51 = s0 ? av[5] : bv[5];
    const float D00 = av[6]*f50, D01 = bv[6]*f50;
    const float D10 = bv[6]*f51, D11 = av[6]*f51;

    u64 bse[8];
    bse[0] = pk2(C000*D00, C001*D00);   // r=0,1
    bse[1] = pk2(C010*D00, C011*D00);   // r=2,3
    bse[2] = pk2(C100*D01, C101*D01);   // r=4,5
    bse[3] = pk2(C110*D01, C111*D01);   // r=6,7
    bse[4] = pk2(C000*D10, C001*D10);   // r=8,9
    bse[5] = pk2(C010*D10, C011*D10);   // r=10,11
    bse[6] = pk2(C100*D11, C101*D11);   // r=12,13
    bse[7] = pk2(C110*D11, C111*D11);   // r=14,15

    // spill for pairs 1..3 (same-thread readback: no syncwarp needed)
#pragma unroll
    for (int p = 0; p < 8; ++p)
        SPILL[lane + 32 * p] = bse[p];

    // ---- channel pairs ----
    const float tsgn = (__popc(llo & 7) & 1) ? -1.0f : 1.0f;
    const int   s8   = llo >> 3;               // read-side bit3 relabel flag
    const u64   FLIPB = 0x8000000080000000ULL;

    // compact u64 transpose map: addr = (j7..4 ^ 8*j3) + 18*j3..0 + 288*j8
    u64* W0 = S64 + llo + 288 * l4;            // writes r<8  : W0[18r]
    u64* W1 = S64 + (llo ^ 8) + 288 * l4;      // writes r>=8 : W1[18r]
    const ulonglong2* RB = (const ulonglong2*)(S64 + 18 * llo + 288 * l4);

    u64 P[4];

#pragma unroll
    for (int pr = 0; pr < 4; ++pr){
        const int o = 2 * pr;
        u64 Z[16];

        // qubit 8 (reg bit0) fused with pair init (regs for pr=0, spill after)
        {
            const float ta = gtan[o][7], tb_ = gtan[o + 1][7];
#pragma unroll
            for (int p = 0; p < 8; ++p){
                const u64 w = (pr == 0) ? bse[p] : SPILL[lane + 32 * p];
                const float a0 = lo2(w), b0 = hi2(w);
                Z[2 * p]     = pk2(fmaf( ta, b0, a0), fmaf( tb_, b0, a0));
                Z[2 * p + 1] = pk2(fmaf(-ta, a0, b0), fmaf(-tb_, a0, b0));
            }
        }
        // qubits 7,6,5 (reg bits 1,2,3)
#pragma unroll
        for (int k = 1; k < 4; ++k){
            const int m   = 1 << k;
            const u64 tb  = gttp[pr][7 - k];
            const u64 ntb = tb ^ FLIPB;
#pragma unroll
            for (int p = 0; p < 16; ++p) if (!(p & m)){
                const u64 A = Z[p], B = Z[p | m];
                Z[p]     = fma2(tb,  B, A);
                Z[p | m] = fma2(ntb, A, B);
            }
        }

        // u64 transpose (swap j7..4 <-> j3..0), conflict-free both directions
        if (pr) __syncwarp();
#pragma unroll
        for (int r = 0; r < 8; ++r)  W0[18 * r] = Z[r];
#pragma unroll
        for (int r = 8; r < 16; ++r) W1[18 * r] = Z[r];
        __syncwarp();

        // read + fused qubit-4 rotation (new reg bit0)
        {
            const u64 tb4  = gttp[pr][3];
            const u64 ntb4 = tb4 ^ FLIPB;
#pragma unroll
            for (int kk = 0; kk < 8; ++kk){
                const ulonglong2 w = RB[kk];
                Z[2 * kk]     = fma2(tb4,  w.y, w.x);
                Z[2 * kk + 1] = fma2(ntb4, w.x, w.y);
            }
        }
        // qubits 3,2 (reg bits 1,2)
#pragma unroll
        for (int k = 1; k < 3; ++k){
            const int m   = 1 << k;
            const u64 tb  = gttp[pr][3 - k];
            const u64 ntb = tb ^ FLIPB;
#pragma unroll
            for (int p = 0; p < 16; ++p) if (!(p & m)){
                const u64 A = Z[p], B = Z[p | m];
                Z[p]     = fma2(tb,  B, A);
                Z[p | m] = fma2(ntb, A, B);
            }
        }
        // qubit 1 (reg bit 3) with s8 role swap (k = r' ^ 8*s8)
        {
            const u64 tb1  = gttp[pr][0];
            const u64 ntb1 = tb1 ^ FLIPB;
            const u64 ta   = s8 ? ntb1 : tb1;
            const u64 tb_  = s8 ? tb1  : ntb1;
#pragma unroll
            for (int p = 0; p < 8; ++p){
                const u64 A = Z[p], B = Z[p | 8];
                Z[p]     = fma2(ta,  B, A);
                Z[p | 8] = fma2(tb_, A, B);
            }
        }

        // signed squares: sign(j) = tsgn * (-1)^popc4(k)
        u64 accE = 0, accO = 0;
        accE = fma2(Z[0],  Z[0],  accE);  accO = fma2(Z[1],  Z[1],  accO);
        accO = fma2(Z[2],  Z[2],  accO);  accE = fma2(Z[3],  Z[3],  accE);
        accO = fma2(Z[4],  Z[4],  accO);  accE = fma2(Z[5],  Z[5],  accE);
        accE = fma2(Z[6],  Z[6],  accE);  accO = fma2(Z[7],  Z[7],  accO);
        accO = fma2(Z[8],  Z[8],  accO);  accE = fma2(Z[9],  Z[9],  accE);
        accE = fma2(Z[10], Z[10], accE);  accO = fma2(Z[11], Z[11], accO);
        accE = fma2(Z[12], Z[12], accE);  accO = fma2(Z[13], Z[13], accO);
        accO = fma2(Z[14], Z[14], accO);  accE = fma2(Z[15], Z[15], accE);

        P[pr] = pk2((lo2(accE) - lo2(accO)) * tsgn,
                    (hi2(accE) - hi2(accO)) * tsgn);
    }

    // ---- partials into (now free) transpose region, validated swizzle ----
    __syncwarp();
#pragma unroll
    for (int pr = 0; pr < 4; ++pr){
        const int o = 2 * pr;
        SF[o * 36       + ((lane + o)     & 31)] = lo2(P[pr]);
        SF[(o + 1) * 36 + ((lane + o + 1) & 31)] = hi2(P[pr]);
    }
    __syncwarp();

    // ---- cooperative 8-channel reduction: 8 LDS + 2 SHFL per thread ----
    {
        const int ch = lane >> 2;
        const int i  = lane & 3;
        float tot = 0.0f;
#pragma unroll
        for (int m = 0; m < 8; ++m)
            tot += SF[ch * 36 + ((8 * i + m + ch) & 31)];
        tot += __shfl_xor_sync(0xffffffffu, tot, 1);
        tot += __shfl_xor_sync(0xffffffffu, tot, 2);
        if (i == 0)
            out[(b * OCH + ch) * LOUT + t] = tot * gK[ch];
    }
}

extern "C" void kernel_launch(void* const* d_in, const int* in_sizes, int n_in,
                              void* d_out, int out_size)
{
    const float* x_ptr  = nullptr;
    const float* th_ptr = nullptr;
    for (int i = 0; i < n_in; ++i){
        if (in_sizes[i] == BATCH * C_CH * LEN) x_ptr  = (const float*)d_in[i];
        else if (in_sizes[i] == OCH * N_Q)     th_ptr = (const float*)d_in[i];
    }
    if (!x_ptr)  x_ptr  = (const float*)d_in[0];
    if (!th_ptr) th_ptr = (const float*)d_in[n_in - 1];

    cudaFuncSetAttribute(qconv_kernel,
                         cudaFuncAttributeMaxDynamicSharedMemorySize, DYNSZ);
    qconv_kernel<<<LOUT, 256, DYNSZ>>>(x_ptr, th_ptr, (float*)d_out);
}

// round 15
// speedup vs baseline: 2.0198x; 1.7817x over previous
#include <cuda_runtime.h>

#define LEN   2048
#define LOUT  2046
#define BATCH 8
#define OCH   8
#define NW    (BATCH * LOUT)     // 16368 windows

// ---- precomputed Pauli-term tables (built by prep_kernel from permref) ----
__device__ int   g_nT;
__device__ int   g_sm[256];      // sin-letter mask (index-bit space, 9 bits)
__device__ int   g_cm[256];      // cos-letter mask
__device__ float g_cf[256 * 8];  // per-term, per-channel weight

// CNOT-ring permutation (replicates reference idx construction; GF(2)-linear)
__device__ __forceinline__ int permref(int id){
#pragma unroll
    for (int c = 0; c < 8; ++c){
        const int bit = (id >> (8 - c)) & 1;
        id ^= bit << (7 - c);
    }
    id ^= (id & 1) << 8;
    return id;
}

// Build surviving Pauli terms:
//  result_o = sum_T [prod_{i in T} cos(th_{8-i}) prod_{i notin T} sin(th_{8-i})]
//             * prod_{i in xs(T)} sin(x_{8-i}) * prod_{i in zs(T)} cos(x_{8-i})
//  xs(T) = A^T (0xFF ^ T),  zs(T) = f^{-1}(T);  term survives iff xs & zs == 0.
__global__ void prep_kernel(const float* __restrict__ theta){
    __shared__ int   F[512];
    __shared__ int   FI[512];
    __shared__ float ct[8][8], st[8][8];      // [o][qubit-1]
    __shared__ int   s_sm[256], s_cm[256];
    __shared__ unsigned char s_alive[256];
    __shared__ float s_cf[256 * 8];

    const int tid = threadIdx.x;              // 512 threads
    F[tid] = permref(tid);
    __syncthreads();
    FI[F[tid]] = tid;                         // f^{-1} table (linear map)
    if (tid < 64){
        const int o = tid >> 3, qm1 = tid & 7;
        float s, c; sincosf(theta[o * 9 + qm1 + 1], &s, &c);   // FULL theta
        ct[o][qm1] = c; st[o][qm1] = s;
    }
    __syncthreads();

    if (tid < 256){
        const int T = tid;
        const int z = 0xFF ^ T;
        int xs = 0;
#pragma unroll
        for (int i = 0; i < 9; ++i)           // (A^T z)_i = <z, A e_i>
            xs |= (__popc(z & F[1 << i]) & 1) << i;
        const int zs = FI[T];
        s_alive[T] = (unsigned char)((xs & zs) == 0);
        s_sm[T] = xs;
        s_cm[T] = zs;
#pragma unroll
        for (int o = 0; o < 8; ++o){
            float w = 1.0f;
#pragma unroll
            for (int i = 0; i < 8; ++i){      // index bit i <-> qubit 8-i
                const int qm1 = 7 - i;        // qubit-1
                w *= ((T >> i) & 1) ? ct[o][qm1] : st[o][qm1];
            }
            s_cf[T * 8 + o] = w;
        }
    }
    __syncthreads();

    if (tid == 0){                            // deterministic compaction
        int n = 0;
        for (int T = 0; T < 256; ++T) if (s_alive[T]){
            g_sm[n] = s_sm[T];
            g_cm[n] = s_cm[T];
            for (int o = 0; o < 8; ++o) g_cf[n * 8 + o] = s_cf[T * 8 + o];
            ++n;
        }
        g_nT = n;
    }
}

__global__ __launch_bounds__(256)
void qconv_main(const float* __restrict__ x, float* __restrict__ out){
    __shared__ int    smk[256], cmk[256];
    __shared__ float4 cf4[512];

    const int tid = threadIdx.x;
    smk[tid] = g_sm[tid];
    cmk[tid] = g_cm[tid];
    cf4[2 * tid]     = ((const float4*)g_cf)[2 * tid];
    cf4[2 * tid + 1] = ((const float4*)g_cf)[2 * tid + 1];
    const int nT = g_nT;
    __syncthreads();

    const int gid = blockIdx.x * 256 + tid;
    if (gid >= NW) return;
    const int b = gid / LOUT;
    const int t = gid - b * LOUT;

    // angles indexed by INDEX BIT i (qubit 8-i); full angle
    float sn[9], cs[9];
#pragma unroll
    for (int i = 0; i < 9; ++i){
        const int q = 8 - i;
        const float xv = x[(b * 3 + q / 3) * LEN + t + q % 3];
        sincosf(xv, &sn[i], &cs[i]);
    }

    float a0 = 0, a1 = 0, a2 = 0, a3 = 0, a4 = 0, a5 = 0, a6 = 0, a7 = 0;
    for (int T = 0; T < nT; ++T){
        const int sm = smk[T], cm = cmk[T];
        float v = 1.0f;
#pragma unroll
        for (int i = 0; i < 9; ++i){
            const float f = ((sm >> i) & 1) ? sn[i]
                          : (((cm >> i) & 1) ? cs[i] : 1.0f);
            v *= f;
        }
        const float4 cA = cf4[2 * T], cB = cf4[2 * T + 1];
        a0 = fmaf(cA.x, v, a0);  a1 = fmaf(cA.y, v, a1);
        a2 = fmaf(cA.z, v, a2);  a3 = fmaf(cA.w, v, a3);
        a4 = fmaf(cB.x, v, a4);  a5 = fmaf(cB.y, v, a5);
        a6 = fmaf(cB.z, v, a6);  a7 = fmaf(cB.w, v, a7);
    }

    float* ob = out + (b * OCH) * LOUT + t;
    ob[0]        = a0;  ob[LOUT]     = a1;
    ob[2 * LOUT] = a2;  ob[3 * LOUT] = a3;
    ob[4 * LOUT] = a4;  ob[5 * LOUT] = a5;
    ob[6 * LOUT] = a6;  ob[7 * LOUT] = a7;
}

extern "C" void kernel_launch(void* const* d_in, const int* in_sizes, int n_in,
                              void* d_out, int out_size)
{
    const float* x_ptr  = nullptr;
    const float* th_ptr = nullptr;
    for (int i = 0; i < n_in; ++i){
        if (in_sizes[i] == BATCH * 3 * LEN)  x_ptr  = (const float*)d_in[i];
        else if (in_sizes[i] == OCH * 9)     th_ptr = (const float*)d_in[i];
    }
    if (!x_ptr)  x_ptr  = (const float*)d_in[0];
    if (!th_ptr) th_ptr = (const float*)d_in[n_in - 1];

    prep_kernel<<<1, 512>>>(th_ptr);
    qconv_main<<<(NW + 255) / 256, 256>>>(x_ptr, (float*)d_out);
}

// round 16
// speedup vs baseline: 3.3075x; 1.6375x over previous
#include <cuda_runtime.h>

#define LEN   2048
#define LOUT  2046
#define BATCH 8
#define OCH   8
#define NW    (BATCH * LOUT)     // 16368 windows

// ---- Pauli-term tables (built by prep_kernel from permref) ----
__device__ int   g_nT;
__device__ int   g_sm[256];      // sin-letter mask (index-bit space, 9 bits)
__device__ int   g_cm[256];      // cos-letter mask
__device__ float g_cf[256 * 8];  // per-term, per-channel weight

// CNOT-ring permutation (replicates reference idx construction; GF(2)-linear)
__device__ __forceinline__ int permref(int id){
#pragma unroll
    for (int c = 0; c < 8; ++c){
        const int bit = (id >> (8 - c)) & 1;
        id ^= bit << (7 - c);
    }
    id ^= (id & 1) << 8;
    return id;
}

// Surviving Pauli terms (same algebra as validated R15):
//  xs(T) = A^T (0xFF ^ T),  zs(T) = f^{-1}(T);  term survives iff xs & zs == 0.
//  Compaction via ballot-scan: deterministic ranks, no serial loop.
__global__ void prep_kernel(const float* __restrict__ theta){
    __shared__ int   F[512];
    __shared__ int   FI[512];
    __shared__ float ct[8][8], st[8][8];      // [o][qubit-1]
    __shared__ int   wcnt[8], woff[8];

    const int tid = threadIdx.x;              // 256 threads
    F[tid]       = permref(tid);
    F[tid + 256] = permref(tid + 256);
    __syncthreads();
    FI[F[tid]]       = tid;                   // f^{-1} (perm is bijective)
    FI[F[tid + 256]] = tid + 256;
    if (tid < 64){
        const int o = tid >> 3, q = tid & 7;
        float s, c; sincosf(theta[o * 9 + q + 1], &s, &c);   // full theta
        ct[o][q] = c; st[o][q] = s;
    }
    __syncthreads();

    const int T = tid;
    const int z = 0xFF ^ T;
    int xs = 0;
#pragma unroll
    for (int i = 0; i < 9; ++i)               // (A^T z)_i = <z, A e_i>
        xs |= (__popc(z & F[1 << i]) & 1) << i;
    const int zs = FI[T];
    const bool alive = (xs & zs) == 0;

    const int lane = tid & 31, w = tid >> 5;
    const unsigned bal = __ballot_sync(0xffffffffu, alive);
    if (lane == 0) wcnt[w] = __popc(bal);
    __syncthreads();
    if (tid == 0){
        int acc = 0;
#pragma unroll
        for (int i = 0; i < 8; ++i){ woff[i] = acc; acc += wcnt[i]; }
        g_nT = acc;
    }
    __syncthreads();

    if (alive){
        const int rank = woff[w] + __popc(bal & ((1u << lane) - 1u));
        g_sm[rank] = xs;
        g_cm[rank] = zs;
#pragma unroll
        for (int o = 0; o < 8; ++o){
            float wv = 1.0f;
#pragma unroll
            for (int i = 0; i < 8; ++i)        // index bit i <-> qubit 8-i
                wv *= ((T >> i) & 1) ? ct[o][7 - i] : st[o][7 - i];
            g_cf[rank * 8 + o] = wv;
        }
    }
}

#define LETT(i) ( ((sm >> (i)) & 1) ? sn[i] : ( ((cm >> (i)) & 1) ? cs[i] : 1.0f ) )

__global__ __launch_bounds__(128)
void qconv_main(const float* __restrict__ x, float* __restrict__ out){
    const int gid = blockIdx.x * 128 + threadIdx.x;
    if (gid >= 2 * NW) return;
    const int wdw  = gid >> 1;                 // window index
    const int half = gid & 1;                  // term-parity half
    const int b = wdw / LOUT;
    const int t = wdw - b * LOUT;

    // angles indexed by INDEX BIT i (qubit 8-i); full angle
    float sn[9], cs[9];
#pragma unroll
    for (int i = 0; i < 9; ++i){
        const int q = 8 - i;
        const float xv = x[(b * 3 + q / 3) * LEN + t + q % 3];
        __sincosf(xv, &sn[i], &cs[i]);
    }

    float a0 = 0, a1 = 0, a2 = 0, a3 = 0, a4 = 0, a5 = 0, a6 = 0, a7 = 0;
    const int nT = g_nT;
    for (int T = half; T < nT; T += 2){
        const int sm = g_sm[T], cm = g_cm[T];
        const float v01 = LETT(0) * LETT(1);
        const float v23 = LETT(2) * LETT(3);
        const float v45 = LETT(4) * LETT(5);
        const float v67 = LETT(6) * LETT(7);
        const float v   = ((v01 * v23) * (v45 * v67)) * LETT(8);

        const float4 cA = ((const float4*)g_cf)[2 * T];
        const float4 cB = ((const float4*)g_cf)[2 * T + 1];
        a0 = fmaf(cA.x, v, a0);  a1 = fmaf(cA.y, v, a1);
        a2 = fmaf(cA.z, v, a2);  a3 = fmaf(cA.w, v, a3);
        a4 = fmaf(cB.x, v, a4);  a5 = fmaf(cB.y, v, a5);
        a6 = fmaf(cB.z, v, a6);  a7 = fmaf(cB.w, v, a7);
    }

    // combine the two halves (lanes 2k / 2k+1 share a window)
    a0 += __shfl_xor_sync(0xffffffffu, a0, 1);
    a1 += __shfl_xor_sync(0xffffffffu, a1, 1);
    a2 += __shfl_xor_sync(0xffffffffu, a2, 1);
    a3 += __shfl_xor_sync(0xffffffffu, a3, 1);
    a4 += __shfl_xor_sync(0xffffffffu, a4, 1);
    a5 += __shfl_xor_sync(0xffffffffu, a5, 1);
    a6 += __shfl_xor_sync(0xffffffffu, a6, 1);
    a7 += __shfl_xor_sync(0xffffffffu, a7, 1);

    if (!half){
        float* ob = out + (b * OCH) * LOUT + t;
        ob[0]        = a0;  ob[LOUT]     = a1;
        ob[2 * LOUT] = a2;  ob[3 * LOUT] = a3;
        ob[4 * LOUT] = a4;  ob[5 * LOUT] = a5;
        ob[6 * LOUT] = a6;  ob[7 * LOUT] = a7;
    }
}

extern "C" void kernel_launch(void* const* d_in, const int* in_sizes, int n_in,
                              void* d_out, int out_size)
{
    const float* x_ptr  = nullptr;
    const float* th_ptr = nullptr;
    for (int i = 0; i < n_in; ++i){
        if (in_sizes[i] == BATCH * 3 * LEN)  x_ptr  = (const float*)d_in[i];
        else if (in_sizes[i] == OCH * 9)     th_ptr = (const float*)d_in[i];
    }
    if (!x_ptr)  x_ptr  = (const float*)d_in[0];
    if (!th_ptr) th_ptr = (const float*)d_in[n_in - 1];

    prep_kernel<<<1, 256>>>(th_ptr);
    qconv_main<<<(2 * NW + 127) / 128, 128>>>(x_ptr, (float*)d_out);
}

// round 17
// speedup vs baseline: 3.9611x; 1.1976x over previous
#include <cuda_runtime.h>

#define LEN   2048
#define LOUT  2046
#define BATCH 8
#define OCH   8
#define NW    (BATCH * LOUT)     // 16368 windows

// ---- Pauli-term tables (built by prep_kernel from permref) ----
__device__ int   g_nT;
__device__ int   g_sm[256];      // sin-letter mask (index-bit space, 9 bits)
__device__ int   g_cm[256];      // cos-letter mask
__device__ float g_cf[256 * 8];  // per-term, per-channel weight

// CNOT-ring permutation (replicates reference idx construction; GF(2)-linear)
__device__ __forceinline__ int permref(int id){
#pragma unroll
    for (int c = 0; c < 8; ++c){
        const int bit = (id >> (8 - c)) & 1;
        id ^= bit << (7 - c);
    }
    id ^= (id & 1) << 8;
    return id;
}

// Surviving Pauli terms (same algebra as validated R15/R16):
//  xs(T) = A^T (0xFF ^ T),  zs(T) = f^{-1}(T);  term survives iff xs & zs == 0.
__global__ void prep_kernel(const float* __restrict__ theta){
    __shared__ int   F[512];
    __shared__ int   FI[512];
    __shared__ float ct[8][8], st[8][8];      // [o][qubit-1]
    __shared__ int   wcnt[8], woff[8];

    const int tid = threadIdx.x;              // 256 threads
    F[tid]       = permref(tid);
    F[tid + 256] = permref(tid + 256);
    __syncthreads();
    FI[F[tid]]       = tid;                   // f^{-1} (perm is bijective)
    FI[F[tid + 256]] = tid + 256;
    if (tid < 64){
        const int o = tid >> 3, q = tid & 7;
        float s, c; sincosf(theta[o * 9 + q + 1], &s, &c);   // full theta
        ct[o][q] = c; st[o][q] = s;
    }
    __syncthreads();

    const int T = tid;
    const int z = 0xFF ^ T;
    int xs = 0;
#pragma unroll
    for (int i = 0; i < 9; ++i)               // (A^T z)_i = <z, A e_i>
        xs |= (__popc(z & F[1 << i]) & 1) << i;
    const int zs = FI[T];
    const bool alive = (xs & zs) == 0;

    const int lane = tid & 31, w = tid >> 5;
    const unsigned bal = __ballot_sync(0xffffffffu, alive);
    if (lane == 0) wcnt[w] = __popc(bal);
    __syncthreads();
    if (tid == 0){
        int acc = 0;
#pragma unroll
        for (int i = 0; i < 8; ++i){ woff[i] = acc; acc += wcnt[i]; }
        g_nT = acc;
    }
    __syncthreads();

    if (alive){
        const int rank = woff[w] + __popc(bal & ((1u << lane) - 1u));
        g_sm[rank] = xs;
        g_cm[rank] = zs;
#pragma unroll
        for (int o = 0; o < 8; ++o){
            float wv = 1.0f;
#pragma unroll
            for (int i = 0; i < 8; ++i)        // index bit i <-> qubit 8-i
                wv *= ((T >> i) & 1) ? ct[o][7 - i] : st[o][7 - i];
            g_cf[rank * 8 + o] = wv;
        }
    }
}

#define LETT(i) ( ((sm >> (i)) & 1) ? sn[i] : ( ((cm >> (i)) & 1) ? cs[i] : 1.0f ) )

__global__ __launch_bounds__(128)
void qconv_main(const float* __restrict__ x, float* __restrict__ out){
    const int gid = blockIdx.x * 128 + threadIdx.x;
    const int wdw  = gid >> 3;                 // window index
    const int oct  = gid & 7;                  // term octant
    const int b = wdw / LOUT;
    const int t = wdw - b * LOUT;

    // angles indexed by INDEX BIT i (qubit 8-i); full angle
    float sn[9], cs[9];
#pragma unroll
    for (int i = 0; i < 9; ++i){
        const int q = 8 - i;
        const float xv = __ldg(&x[(b * 3 + q / 3) * LEN + t + q % 3]);
        __sincosf(xv, &sn[i], &cs[i]);
    }

    float a0 = 0, a1 = 0, a2 = 0, a3 = 0, a4 = 0, a5 = 0, a6 = 0, a7 = 0;
    const int nT = g_nT;
    for (int T = oct; T < nT; T += 8){
        const int sm = __ldg(&g_sm[T]), cm = __ldg(&g_cm[T]);
        const float v01 = LETT(0) * LETT(1);
        const float v23 = LETT(2) * LETT(3);
        const float v45 = LETT(4) * LETT(5);
        const float v67 = LETT(6) * LETT(7);
        const float v   = ((v01 * v23) * (v45 * v67)) * LETT(8);

        const float4 cA = __ldg(&((const float4*)g_cf)[2 * T]);
        const float4 cB = __ldg(&((const float4*)g_cf)[2 * T + 1]);
        a0 = fmaf(cA.x, v, a0);  a1 = fmaf(cA.y, v, a1);
        a2 = fmaf(cA.z, v, a2);  a3 = fmaf(cA.w, v, a3);
        a4 = fmaf(cB.x, v, a4);  a5 = fmaf(cB.y, v, a5);
        a6 = fmaf(cB.z, v, a6);  a7 = fmaf(cB.w, v, a7);
    }

    // combine the 8 octants (lanes 8k..8k+7 share a window); fixed order
#pragma unroll
    for (int d = 1; d < 8; d <<= 1){
        a0 += __shfl_xor_sync(0xffffffffu, a0, d);
        a1 += __shfl_xor_sync(0xffffffffu, a1, d);
        a2 += __shfl_xor_sync(0xffffffffu, a2, d);
        a3 += __shfl_xor_sync(0xffffffffu, a3, d);
        a4 += __shfl_xor_sync(0xffffffffu, a4, d);
        a5 += __shfl_xor_sync(0xffffffffu, a5, d);
        a6 += __shfl_xor_sync(0xffffffffu, a6, d);
        a7 += __shfl_xor_sync(0xffffffffu, a7, d);
    }

    if (oct == 0){
        float* ob = out + (b * OCH) * LOUT + t;
        ob[0]        = a0;  ob[LOUT]     = a1;
        ob[2 * LOUT] = a2;  ob[3 * LOUT] = a3;
        ob[4 * LOUT] = a4;  ob[5 * LOUT] = a5;
        ob[6 * LOUT] = a6;  ob[7 * LOUT] = a7;
    }
}

extern "C" void kernel_launch(void* const* d_in, const int* in_sizes, int n_in,
                              void* d_out, int out_size)
{
    const float* x_ptr  = nullptr;
    const float* th_ptr = nullptr;
    for (int i = 0; i < n_in; ++i){
        if (in_sizes[i] == BATCH * 3 * LEN)  x_ptr  = (const float*)d_in[i];
        else if (in_sizes[i] == OCH * 9)     th_ptr = (const float*)d_in[i];
    }
    if (!x_ptr)  x_ptr  = (const float*)d_in[0];
    if (!th_ptr) th_ptr = (const float*)d_in[n_in - 1];

    prep_kernel<<<1, 256>>>(th_ptr);
    qconv_main<<<(8 * NW) / 128, 128>>>(x_ptr, (float*)d_out);   // 1023 blocks
}